// round 2
// baseline (speedup 1.0000x reference)
#include <cuda_runtime.h>
#include <cuda_bf16.h>

// Problem constants (from reference):
//   D_MODEL = 2048, QUAT_DIM = 512, B = 4, T = 4096
// Inputs (metadata order): x [B,T,2048] f32, q_left [4,512] f32,
//                          q_right [4,512] f32, spectral_gate [512] f32
// Output: [B,T,2048] f32
//
// Math: spectral_gate broadcasts uniformly over the FFT frequency axis, so
// ifft(fft(x)*g).real == g*x exactly. The two Hamilton products are linear in
// x, so the whole op is a per-feature 4x4 matrix applied to (w,x,y,z).

#define QD 512
#define NBT (4 * 4096)  // B*T = 16384

// Precomputed fused matrices: layout [row*4+col][QD] for coalesced float4 reads.
__device__ float g_M[16 * QD];

__global__ void build_matrices_kernel(const float* __restrict__ ql,
                                      const float* __restrict__ qr,
                                      const float* __restrict__ gate) {
    int d = blockIdx.x * blockDim.x + threadIdx.x;
    if (d >= QD) return;

    float lw = ql[0 * QD + d], lx = ql[1 * QD + d], ly = ql[2 * QD + d], lz = ql[3 * QD + d];
    float rw = qr[0 * QD + d], rx = qr[1 * QD + d], ry = qr[2 * QD + d], rz = qr[3 * QD + d];

    float ln = rsqrtf(lw * lw + lx * lx + ly * ly + lz * lz + 1e-8f);
    lw *= ln; lx *= ln; ly *= ln; lz *= ln;

    float rn = rsqrtf(rw * rw + rx * rx + ry * ry + rz * rz + 1e-8f);
    // conjugate: negate x,y,z
    rw *= rn; rx = -rx * rn; ry = -ry * rn; rz = -rz * rn;

    // x_right = x (hamilton) r  ->  R matrix (rows: output comp, cols: input comp)
    float R[4][4] = {
        { rw, -rx, -ry, -rz},
        { rx,  rw,  rz, -ry},
        { ry, -rz,  rw,  rx},
        { rz,  ry, -rx,  rw}
    };
    // x_rot = l (hamilton) v  ->  L matrix
    float L[4][4] = {
        { lw, -lx, -ly, -lz},
        { lx,  lw, -lz,  ly},
        { ly,  lz,  lw, -lx},
        { lz, -ly,  lx,  lw}
    };

    float g = gate[d];
#pragma unroll
    for (int r = 0; r < 4; r++) {
#pragma unroll
        for (int c = 0; c < 4; c++) {
            float m = 0.0f;
#pragma unroll
            for (int k = 0; k < 4; k++) m = fmaf(L[r][k], R[k][c], m);
            g_M[(r * 4 + c) * QD + d] = g * m;
        }
    }
}

// One block per (b,t) row; 128 threads, each handles 4 consecutive features
// via float4. All global accesses are fully coalesced.
__global__ void __launch_bounds__(128)
evolve_kernel(const float* __restrict__ x, float* __restrict__ out) {
    int bt = blockIdx.x;
    int d4 = threadIdx.x * 4;  // starting feature index (multiple of 4)

    const float* xp = x + (size_t)bt * 2048;
    float* op = out + (size_t)bt * 2048;

    float4 in[4];
#pragma unroll
    for (int c = 0; c < 4; c++)
        in[c] = *reinterpret_cast<const float4*>(xp + c * QD + d4);

#pragma unroll
    for (int r = 0; r < 4; r++) {
        float4 a = make_float4(0.f, 0.f, 0.f, 0.f);
#pragma unroll
        for (int c = 0; c < 4; c++) {
            float4 m = *reinterpret_cast<const float4*>(&g_M[(r * 4 + c) * QD + d4]);
            a.x = fmaf(m.x, in[c].x, a.x);
            a.y = fmaf(m.y, in[c].y, a.y);
            a.z = fmaf(m.z, in[c].z, a.z);
            a.w = fmaf(m.w, in[c].w, a.w);
        }
        *reinterpret_cast<float4*>(op + r * QD + d4) = a;
    }
}

extern "C" void kernel_launch(void* const* d_in, const int* in_sizes, int n_in,
                              void* d_out, int out_size) {
    const float* x    = (const float*)d_in[0];
    const float* ql   = (const float*)d_in[1];
    const float* qr   = (const float*)d_in[2];
    const float* gate = (const float*)d_in[3];
    float* out = (float*)d_out;

    build_matrices_kernel<<<1, QD>>>(ql, qr, gate);
    evolve_kernel<<<NBT, 128>>>(x, out);
}